// round 13
// baseline (speedup 1.0000x reference)
#include <cuda_runtime.h>
#include <cuda_bf16.h>
#include <cstdint>

#define BB 32
#define NN 2048
#define DD 512
#define EE 512
#define VV 32000
#define TT 32
#define NSTEP 31
#define MM (NSTEP * BB)   // 992

typedef unsigned long long ull;

// ---------------- scratch ----------------------------------------------------
__device__ float g_h[BB * DD];
__device__ float g_Hall[MM * DD];
__device__ float g_HW[MM * DD];
__device__ float g_scores[MM * NN];         // 8.1 MB
__device__ float g_gx[MM * 4 * DD];         // 8.1 MB  (x-side gates + biases)
__device__ float g_gp[8 * BB * 4 * DD];     // 2 MB    (h-side partials)
__device__ float g_h0part[4 * BB * DD];
__device__ float g_cntpad[BB];
__device__ float g_cntptr[BB];
__device__ int   g_mask_mode;
__device__ unsigned g_cnt8[8 * 32];         // barrier counters, 1 per 128B line

// ---------------- helpers -----------------------------------------------------
__device__ __forceinline__ bool getmask(const void* p, int idx) {
    int m = g_mask_mode;
    if (m == 1) return ((const int*)p)[idx] != 0;
    if (m == 2) return ((const float*)p)[idx] != 0.0f;
    return ((const unsigned char*)p)[idx] != 0;
}
__device__ __forceinline__ float sigm(float x) { return 1.0f / (1.0f + expf(-x)); }

__device__ __forceinline__ ull ld2(const float* p) { return *(const ull*)p; }
__device__ __forceinline__ ull fma2(ull a, ull b, ull c) {
    ull d;
    asm("fma.rn.f32x2 %0, %1, %2, %3;" : "=l"(d) : "l"(a), "l"(b), "l"(c));
    return d;
}
__device__ __forceinline__ float sum2(ull v) {
    return __uint_as_float((unsigned)v) + __uint_as_float((unsigned)(v >> 32));
}

// ---------------- setup -------------------------------------------------------
__global__ void detect_kernel(const int* pad_as_int) {
    int tid = threadIdx.x;
    if (tid < 8) g_cnt8[tid * 32] = 0;
    if (tid == 0) {
        int v = pad_as_int[0];
        g_mask_mode = (v == 1) ? 1 : ((v == 0x3F800000) ? 2 : 0);
    }
}

__global__ void sos_kernel(float* out, const int* sosp) {
    int b = threadIdx.x;
    if (b < BB) out[(size_t)b * VV + sosp[0]] = 1.0f;
}

// ---------------- mega kernel: xgemm || h0part || counts || zero --------------
// grid 1312 x 256:
//   [0,512):    xgemm  gates_x[m][R] = emb[tok(m)]·W_ih[R] + b_ih + b_hh
//   [512,768):  h0part partial masked sums of enc
//   [768,800):  counts pad/pointer counts
//   [800,1312): zero   d_out
__global__ void __launch_bounds__(256) mega_kernel(
        const float* __restrict__ emb, const float* __restrict__ Wih,
        const float* __restrict__ bih, const float* __restrict__ bhh,
        const int* __restrict__ target, const int* __restrict__ sosp,
        const float* __restrict__ enc, const void* pad, const void* ptrm,
        float4* __restrict__ outz, int n4) {
    __shared__ float Ws[2][64][34];
    __shared__ float Xs[2][64][34];
    __shared__ int toks[64];
    __shared__ int red1[256], red2[256];
    int tid = threadIdx.x;
    int bid = blockIdx.x;

    if (bid < 512) {
        // ---------------- xgemm ----------------
        int Rbase = (bid & 31) * 64;
        int mbase = (bid >> 5) * 64;
        if (tid < 64) {
            int m = mbase + tid;
            int t = m >> 5, b = m & 31;
            int tok = sosp[0];
            if (m < MM && t > 0) tok = target[t * BB + b];
            toks[tid] = tok;
        }
        __syncthreads();
        #pragma unroll
        for (int q = 0; q < 2; q++) {
            int i = tid + 256 * q;
            int row = i >> 3, c4 = i & 7;
            float4 w = *(const float4*)&Wih[(size_t)(Rbase + row) * 512 + c4 * 4];
            float4 x = *(const float4*)&emb[(size_t)toks[row] * 512 + c4 * 4];
            *(float2*)&Ws[0][row][c4 * 4]     = make_float2(w.x, w.y);
            *(float2*)&Ws[0][row][c4 * 4 + 2] = make_float2(w.z, w.w);
            *(float2*)&Xs[0][row][c4 * 4]     = make_float2(x.x, x.y);
            *(float2*)&Xs[0][row][c4 * 4 + 2] = make_float2(x.z, x.w);
        }
        __syncthreads();
        int rl = tid & 15, mg = tid >> 4;
        ull acc[4][4] = {};
        float4 wst[2], xst[2];
        for (int kt = 0; kt < 16; kt++) {
            int cur = kt & 1;
            if (kt < 15) {
                int k0 = (kt + 1) * 32;
                #pragma unroll
                for (int q = 0; q < 2; q++) {
                    int i = tid + 256 * q;
                    int row = i >> 3, c4 = i & 7;
                    wst[q] = *(const float4*)&Wih[(size_t)(Rbase + row) * 512 + k0 + c4 * 4];
                    xst[q] = *(const float4*)&emb[(size_t)toks[row] * 512 + k0 + c4 * 4];
                }
            }
            #pragma unroll
            for (int kp = 0; kp < 16; kp++) {
                ull wv[4], xv[4];
                #pragma unroll
                for (int i = 0; i < 4; i++) wv[i] = ld2(&Ws[cur][rl + 16 * i][kp * 2]);
                #pragma unroll
                for (int j = 0; j < 4; j++) xv[j] = ld2(&Xs[cur][mg * 4 + j][kp * 2]);
                #pragma unroll
                for (int i = 0; i < 4; i++)
                    #pragma unroll
                    for (int j = 0; j < 4; j++)
                        acc[i][j] = fma2(wv[i], xv[j], acc[i][j]);
            }
            if (kt < 15) {
                __syncthreads();
                int nb = cur ^ 1;
                #pragma unroll
                for (int q = 0; q < 2; q++) {
                    int i = tid + 256 * q;
                    int row = i >> 3, c4 = i & 7;
                    *(float2*)&Ws[nb][row][c4 * 4]     = make_float2(wst[q].x, wst[q].y);
                    *(float2*)&Ws[nb][row][c4 * 4 + 2] = make_float2(wst[q].z, wst[q].w);
                    *(float2*)&Xs[nb][row][c4 * 4]     = make_float2(xst[q].x, xst[q].y);
                    *(float2*)&Xs[nb][row][c4 * 4 + 2] = make_float2(xst[q].z, xst[q].w);
                }
                __syncthreads();
            }
        }
        #pragma unroll
        for (int j = 0; j < 4; j++) {
            int m = mbase + mg * 4 + j;
            if (m >= MM) continue;
            #pragma unroll
            for (int i = 0; i < 4; i++) {
                int R = Rbase + rl + 16 * i;
                g_gx[((size_t)m << 11) + R] = sum2(acc[i][j]) + bih[R] + bhh[R];
            }
        }
    } else if (bid < 768) {
        // ---------------- h0part ----------------
        int u = bid - 512;
        int dc = u & 1, b = (u >> 1) & 31, z = u >> 6;
        int d = dc * 256 + tid;
        float acc = 0.0f;
        int n0 = z * (NN / 4);
        for (int n = n0; n < n0 + NN / 4; n++) {
            if (getmask(pad, b * NN + n))
                acc += enc[((size_t)(b * NN + n)) * DD + d];
        }
        g_h0part[((z * BB) + b) * DD + d] = acc;
    } else if (bid < 800) {
        // ---------------- counts ----------------
        int b = bid - 768;
        int c1 = 0, c2 = 0;
        for (int n = tid; n < NN; n += 256) {
            c1 += getmask(pad, b * NN + n) ? 1 : 0;
            c2 += getmask(ptrm, b * NN + n) ? 1 : 0;
        }
        red1[tid] = c1; red2[tid] = c2; __syncthreads();
        for (int s = 128; s > 0; s >>= 1) {
            if (tid < s) { red1[tid] += red1[tid + s]; red2[tid] += red2[tid + s]; }
            __syncthreads();
        }
        if (tid == 0) { g_cntpad[b] = (float)red1[0]; g_cntptr[b] = (float)red2[0]; }
    } else {
        // ---------------- zero d_out ----------------
        int zb = bid - 800;
        int idx = zb * 256 + tid;
        int stride = 512 * 256;
        float4 z4 = {0.f, 0.f, 0.f, 0.f};
        for (int i = idx; i < n4; i += stride) outz[i] = z4;
    }
}

// --------- grid barrier: 8-way split RMW arrival + read-only acquire poll ----
__device__ __forceinline__ void gbar(unsigned target) {
    __threadfence();
    __syncthreads();
    if (threadIdx.x == 0) {
        atomicAdd(&g_cnt8[(blockIdx.x & 7) * 32], 1u);
        unsigned ssum;
        do {
            ssum = 0;
            #pragma unroll
            for (int i = 0; i < 8; i++) {
                unsigned v;
                asm volatile("ld.acquire.gpu.global.u32 %0, [%1];"
                             : "=r"(v) : "l"(&g_cnt8[i * 32]) : "memory");
                ssum += v;
            }
        } while (ssum < target);
        __threadfence();
    }
    __syncthreads();
}

// ---------------- persistent LSTM recurrence (R12 core, new barrier) ----------
// 128 blocks x 256 threads. block = (dt = bid>>3, s = bid&7).
__global__ void __launch_bounds__(256) lstm_persistent(const float* __restrict__ Whh) {
    __shared__ float Wsm[128][66];
    __shared__ float hs[32][66];
    int tid = threadIdx.x;
    int bid = blockIdx.x;
    int dt = bid >> 3, s = bid & 7;
    int k0 = s * 64;

    // W_hh slice into smem once
    for (int i = tid; i < 128 * 64; i += 256) {
        int lr = i >> 6, kk = i & 63;
        int R = ((lr >> 5) << 9) + (dt << 5) + (lr & 31);
        Wsm[lr][kk] = Whh[(size_t)R * 512 + k0 + kk];
    }

    // h0 finalize for owned (pb, pd)
    float creg = 0.f;
    int pd = 0, pb = 0;
    if (tid < 128) {
        int idx = bid * 128 + tid;
        pd = idx & 511; pb = idx >> 9;
        float ssum = 0.f;
        #pragma unroll
        for (int z = 0; z < 4; z++) ssum += g_h0part[(z * BB + pb) * DD + pd];
        float h0 = ssum / g_cntpad[pb];
        creg = h0;
        g_h[pb * DD + pd] = h0;
    }
    gbar(128);

    int tx = tid & 31;   // lr = tx + 32*j
    int ty = tid >> 5;   // b = ty*4 + i
    unsigned cnt = 128;

    for (int t = 0; t < NSTEP; t++) {
        // stage h slice [32 b][64 k]
        for (int i = tid; i < 32 * 64; i += 256) {
            int b = i >> 6, kk = i & 63;
            hs[b][kk] = g_h[b * DD + k0 + kk];
        }
        __syncthreads();

        ull acc[4][4] = {};
        #pragma unroll 8
        for (int kp = 0; kp < 32; kp++) {
            ull hv[4], wv[4];
            #pragma unroll
            for (int i = 0; i < 4; i++) hv[i] = ld2(&hs[ty * 4 + i][kp * 2]);
            #pragma unroll
            for (int j = 0; j < 4; j++) wv[j] = ld2(&Wsm[tx + 32 * j][kp * 2]);
            #pragma unroll
            for (int i = 0; i < 4; i++)
                #pragma unroll
                for (int j = 0; j < 4; j++)
                    acc[i][j] = fma2(hv[i], wv[j], acc[i][j]);
        }
        #pragma unroll
        for (int i = 0; i < 4; i++) {
            int b = ty * 4 + i;
            #pragma unroll
            for (int j = 0; j < 4; j++)
                g_gp[((s * BB + b) << 11) + (j << 9) + (dt << 5) + tx] = sum2(acc[i][j]);
        }

        cnt += 128; gbar(cnt);   // partials ready

        if (tid < 128) {
            const float* gx = g_gx + ((size_t)(t * BB + pb) << 11);
            float gi = gx[pd], gf = gx[512 + pd], gg = gx[1024 + pd], go = gx[1536 + pd];
            #pragma unroll
            for (int ss = 0; ss < 8; ss++) {
                const float* gp = g_gp + ((size_t)(ss * BB + pb) << 11);
                gi += gp[pd]; gf += gp[512 + pd]; gg += gp[1024 + pd]; go += gp[1536 + pd];
            }
            float cn = sigm(gf) * creg + sigm(gi) * tanhf(gg);
            float hn = sigm(go) * tanhf(cn);
            creg = cn;
            g_h[pb * DD + pd] = hn;
            g_Hall[((size_t)(t * BB + pb) << 9) + pd] = hn;
        }

        cnt += 128; gbar(cnt);   // h ready
    }
}

// ---------------- hw: HW[m][n] = Hall[m]·W_att[n] ----------------------------
__global__ void __launch_bounds__(256) hw_kernel(const float* __restrict__ Watt) {
    __shared__ float As[64][66];
    __shared__ float Ws[64][66];
    int tid = threadIdx.x;
    int mbase = blockIdx.x * 64;
    int nbase = blockIdx.y * 64;
    int tx = tid & 15;
    int ty = tid >> 4;
    ull acc[4][4] = {};
    for (int k0 = 0; k0 < 512; k0 += 32) {
        __syncthreads();
        #pragma unroll
        for (int i = 0; i < 8; i++) {
            int lin = tid + 256 * i;
            int row = lin >> 5, c = lin & 31;
            int m = mbase + row;
            As[row][c] = (m < MM) ? g_Hall[((size_t)m << 9) + k0 + c] : 0.f;
            Ws[row][c] = Watt[(size_t)(nbase + row) * 512 + k0 + c];
        }
        __syncthreads();
        #pragma unroll
        for (int kp = 0; kp < 16; kp++) {
            ull av[4], wv[4];
            #pragma unroll
            for (int jj = 0; jj < 4; jj++) av[jj] = ld2(&As[ty * 4 + jj][kp * 2]);
            #pragma unroll
            for (int i = 0; i < 4; i++) wv[i] = ld2(&Ws[tx + 16 * i][kp * 2]);
            #pragma unroll
            for (int i = 0; i < 4; i++)
                #pragma unroll
                for (int jj = 0; jj < 4; jj++)
                    acc[i][jj] = fma2(av[jj], wv[i], acc[i][jj]);
        }
    }
    #pragma unroll
    for (int jj = 0; jj < 4; jj++) {
        int m = mbase + ty * 4 + jj;
        if (m >= MM) continue;
        #pragma unroll
        for (int i = 0; i < 4; i++)
            g_HW[((size_t)m << 9) + nbase + tx + 16 * i] = sum2(acc[i][jj]);
    }
}

// ---------------- scores[t][b][n] = enc[b][n]·HW[t*B+b] ----------------------
__global__ void __launch_bounds__(256) scores_kernel(const float* __restrict__ enc) {
    __shared__ float Es[256][34];
    __shared__ float Hs[32][34];
    int tid = threadIdx.x;
    int nbase = blockIdx.x << 8;
    int b = blockIdx.y;
    int nl = tid & 31;
    int tg = tid >> 5;
    ull acc[8][4] = {};
    for (int k0 = 0; k0 < 512; k0 += 32) {
        __syncthreads();
        #pragma unroll
        for (int i = 0; i < 16; i++) {
            int lin = tid + 256 * i;
            int row = lin >> 4, c2 = lin & 15;
            *(ull*)&Es[row][c2 * 2] =
                ld2(&enc[((size_t)(b * NN + nbase + row) << 9) + k0 + c2 * 2]);
        }
        #pragma unroll
        for (int i = 0; i < 2; i++) {
            int lin = tid + 256 * i;
            int row = lin >> 4, c2 = lin & 15;
            *(ull*)&Hs[row][c2 * 2] = (row < NSTEP)
                ? ld2(&g_HW[((size_t)(row * BB + b) << 9) + k0 + c2 * 2]) : 0ull;
        }
        __syncthreads();
        #pragma unroll
        for (int kp = 0; kp < 16; kp++) {
            ull ev[8], hv[4];
            #pragma unroll
            for (int i = 0; i < 8; i++) ev[i] = ld2(&Es[nl + 32 * i][kp * 2]);
            #pragma unroll
            for (int jj = 0; jj < 4; jj++) hv[jj] = ld2(&Hs[tg * 4 + jj][kp * 2]);
            #pragma unroll
            for (int i = 0; i < 8; i++)
                #pragma unroll
                for (int jj = 0; jj < 4; jj++)
                    acc[i][jj] = fma2(ev[i], hv[jj], acc[i][jj]);
        }
    }
    #pragma unroll
    for (int jj = 0; jj < 4; jj++) {
        int t = tg * 4 + jj;
        if (t >= NSTEP) continue;
        #pragma unroll
        for (int i = 0; i < 8; i++)
            g_scores[((size_t)(t * BB + b) << 11) + nbase + nl + 32 * i] = sum2(acc[i][jj]);
    }
}

// ---------------- softmax + threshold + scatter + eos ------------------------
__global__ void softmax_scatter_kernel(const void* ptrmask,
                                       const int* __restrict__ token_ids,
                                       const int* __restrict__ eosp,
                                       float* __restrict__ out) {
    int t = blockIdx.x, b = blockIdx.y, tid = threadIdx.x;
    __shared__ float sp[NN];
    __shared__ float red[256];
    const float* sc = g_scores + ((size_t)(t * BB) + b) * NN;

    float m = -1e30f;
    for (int n = tid; n < NN; n += 256) {
        bool pm = getmask(ptrmask, b * NN + n);
        float s = pm ? sc[n] : -1e30f;
        sp[n] = s;
        m = fmaxf(m, s);
    }
    red[tid] = m; __syncthreads();
    for (int s = 128; s > 0; s >>= 1) {
        if (tid < s) red[tid] = fmaxf(red[tid], red[tid + s]);
        __syncthreads();
    }
    m = red[0]; __syncthreads();

    float lsum = 0.f;
    for (int n = tid; n < NN; n += 256) {
        float s = sp[n];
        float e = (s > -1e29f) ? expf(s - m) : 0.f;
        sp[n] = e;
        lsum += e;
    }
    red[tid] = lsum; __syncthreads();
    for (int s = 128; s > 0; s >>= 1) {
        if (tid < s) red[tid] += red[tid + s];
        __syncthreads();
    }
    float sum = red[0];
    float thr = 1.0f / g_cntptr[b];
    float* orow = out + ((size_t)(t + 1)) * BB * VV + (size_t)b * VV;
    __syncthreads();

    float ks = 0.f;
    for (int n = tid; n < NN; n += 256) {
        float e = sp[n];
        if (e > 0.f) {
            float p = e / sum;
            if (p >= thr) {
                atomicAdd(&orow[token_ids[b * NN + n]], p);
                ks += p;
            }
        }
    }
    red[tid] = ks; __syncthreads();
    for (int s = 128; s > 0; s >>= 1) {
        if (tid < s) red[tid] += red[tid + s];
        __syncthreads();
    }
    if (tid == 0) {
        __threadfence();
        orow[eosp[0]] = 1.0f - red[0];
    }
}

// ---------------- host launcher ----------------------------------------------
extern "C" void kernel_launch(void* const* d_in, const int* in_sizes, int n_in,
                              void* d_out, int out_size) {
    const float* enc    = (const float*)d_in[0];
    const float* emb    = (const float*)d_in[1];
    const float* W_ih   = (const float*)d_in[2];
    const float* W_hh   = (const float*)d_in[3];
    const float* b_ih   = (const float*)d_in[4];
    const float* b_hh   = (const float*)d_in[5];
    const float* W_att  = (const float*)d_in[6];
    const void*  pad    = d_in[7];
    const void*  ptr    = d_in[8];
    const int*   tokid  = (const int*)d_in[9];
    const int*   target = (const int*)d_in[10];
    const int*   sosp   = (const int*)d_in[11];
    const int*   eosp   = (const int*)d_in[12];
    float* out = (float*)d_out;

    detect_kernel<<<1, 32>>>((const int*)pad);

    int n4 = (TT * BB * VV) / 4;
    mega_kernel<<<1312, 256>>>(emb, W_ih, b_ih, b_hh, target, sosp,
                               enc, pad, ptr, (float4*)out, n4);
    sos_kernel<<<1, 32>>>(out, sosp);

    lstm_persistent<<<128, 256>>>(W_hh);

    {
        dim3 g(16, 8);
        hw_kernel<<<g, 256>>>(W_att);
    }
    {
        dim3 g(8, BB);
        scores_kernel<<<g, 256>>>(enc);
    }
    {
        dim3 g(NSTEP, BB);
        softmax_scatter_kernel<<<g, 256>>>(ptr, tokid, eosp, out);
    }
}

// round 14
// speedup vs baseline: 1.0987x; 1.0987x over previous
#include <cuda_runtime.h>
#include <cuda_bf16.h>
#include <cstdint>

#define BB 32
#define NN 2048
#define DD 512
#define EE 512
#define VV 32000
#define TT 32
#define NSTEP 31
#define MM (NSTEP * BB)   // 992

typedef unsigned long long ull;

// ---------------- scratch ----------------------------------------------------
__device__ float g_h[BB * DD];
__device__ float g_Hall[MM * DD];
__device__ float g_HW[MM * DD];
__device__ float g_scores[MM * NN];         // 8.1 MB
__device__ float g_gx[MM * 4 * DD];         // 8.1 MB  (x-side gates + biases)
__device__ float g_gp[8 * BB * 4 * DD];     // 2 MB    (h-side partials)
__device__ float g_h0part[4 * BB * DD];
__device__ float g_cntpad[BB];
__device__ float g_cntptr[BB];
__device__ int   g_mask_mode;
__device__ unsigned g_barcnt;

// ---------------- helpers -----------------------------------------------------
__device__ __forceinline__ bool getmask(const void* p, int idx) {
    int m = g_mask_mode;
    if (m == 1) return ((const int*)p)[idx] != 0;
    if (m == 2) return ((const float*)p)[idx] != 0.0f;
    return ((const unsigned char*)p)[idx] != 0;
}
__device__ __forceinline__ float sigm(float x) { return 1.0f / (1.0f + expf(-x)); }

__device__ __forceinline__ ull ld2(const float* p) { return *(const ull*)p; }
__device__ __forceinline__ ull fma2(ull a, ull b, ull c) {
    ull d;
    asm("fma.rn.f32x2 %0, %1, %2, %3;" : "=l"(d) : "l"(a), "l"(b), "l"(c));
    return d;
}
__device__ __forceinline__ float sum2(ull v) {
    return __uint_as_float((unsigned)v) + __uint_as_float((unsigned)(v >> 32));
}
__device__ __forceinline__ uint32_t ctarank() {
    uint32_t r;
    asm("mov.u32 %0, %%cluster_ctarank;" : "=r"(r));
    return r;
}

// ---------------- setup -------------------------------------------------------
__global__ void detect_kernel(const int* pad_as_int) {
    if (threadIdx.x == 0) {
        int v = pad_as_int[0];
        g_mask_mode = (v == 1) ? 1 : ((v == 0x3F800000) ? 2 : 0);
        g_barcnt = 0;
    }
}

__global__ void sos_kernel(float* out, const int* sosp) {
    int b = threadIdx.x;
    if (b < BB) out[(size_t)b * VV + sosp[0]] = 1.0f;
}

// ---------------- mega kernel: xgemm || h0part || counts || zero --------------
__global__ void __launch_bounds__(256) mega_kernel(
        const float* __restrict__ emb, const float* __restrict__ Wih,
        const float* __restrict__ bih, const float* __restrict__ bhh,
        const int* __restrict__ target, const int* __restrict__ sosp,
        const float* __restrict__ enc, const void* pad, const void* ptrm,
        float4* __restrict__ outz, int n4) {
    __shared__ float Ws[2][64][34];
    __shared__ float Xs[2][64][34];
    __shared__ int toks[64];
    __shared__ int red1[256], red2[256];
    int tid = threadIdx.x;
    int bid = blockIdx.x;

    if (bid < 512) {
        int Rbase = (bid & 31) * 64;
        int mbase = (bid >> 5) * 64;
        if (tid < 64) {
            int m = mbase + tid;
            int t = m >> 5, b = m & 31;
            int tok = sosp[0];
            if (m < MM && t > 0) tok = target[t * BB + b];
            toks[tid] = tok;
        }
        __syncthreads();
        #pragma unroll
        for (int q = 0; q < 2; q++) {
            int i = tid + 256 * q;
            int row = i >> 3, c4 = i & 7;
            float4 w = *(const float4*)&Wih[(size_t)(Rbase + row) * 512 + c4 * 4];
            float4 x = *(const float4*)&emb[(size_t)toks[row] * 512 + c4 * 4];
            *(float2*)&Ws[0][row][c4 * 4]     = make_float2(w.x, w.y);
            *(float2*)&Ws[0][row][c4 * 4 + 2] = make_float2(w.z, w.w);
            *(float2*)&Xs[0][row][c4 * 4]     = make_float2(x.x, x.y);
            *(float2*)&Xs[0][row][c4 * 4 + 2] = make_float2(x.z, x.w);
        }
        __syncthreads();
        int rl = tid & 15, mg = tid >> 4;
        ull acc[4][4] = {};
        float4 wst[2], xst[2];
        for (int kt = 0; kt < 16; kt++) {
            int cur = kt & 1;
            if (kt < 15) {
                int k0 = (kt + 1) * 32;
                #pragma unroll
                for (int q = 0; q < 2; q++) {
                    int i = tid + 256 * q;
                    int row = i >> 3, c4 = i & 7;
                    wst[q] = *(const float4*)&Wih[(size_t)(Rbase + row) * 512 + k0 + c4 * 4];
                    xst[q] = *(const float4*)&emb[(size_t)toks[row] * 512 + k0 + c4 * 4];
                }
            }
            #pragma unroll
            for (int kp = 0; kp < 16; kp++) {
                ull wv[4], xv[4];
                #pragma unroll
                for (int i = 0; i < 4; i++) wv[i] = ld2(&Ws[cur][rl + 16 * i][kp * 2]);
                #pragma unroll
                for (int j = 0; j < 4; j++) xv[j] = ld2(&Xs[cur][mg * 4 + j][kp * 2]);
                #pragma unroll
                for (int i = 0; i < 4; i++)
                    #pragma unroll
                    for (int j = 0; j < 4; j++)
                        acc[i][j] = fma2(wv[i], xv[j], acc[i][j]);
            }
            if (kt < 15) {
                __syncthreads();
                int nb = cur ^ 1;
                #pragma unroll
                for (int q = 0; q < 2; q++) {
                    int i = tid + 256 * q;
                    int row = i >> 3, c4 = i & 7;
                    *(float2*)&Ws[nb][row][c4 * 4]     = make_float2(wst[q].x, wst[q].y);
                    *(float2*)&Ws[nb][row][c4 * 4 + 2] = make_float2(wst[q].z, wst[q].w);
                    *(float2*)&Xs[nb][row][c4 * 4]     = make_float2(xst[q].x, xst[q].y);
                    *(float2*)&Xs[nb][row][c4 * 4 + 2] = make_float2(xst[q].z, xst[q].w);
                }
                __syncthreads();
            }
        }
        #pragma unroll
        for (int j = 0; j < 4; j++) {
            int m = mbase + mg * 4 + j;
            if (m >= MM) continue;
            #pragma unroll
            for (int i = 0; i < 4; i++) {
                int R = Rbase + rl + 16 * i;
                g_gx[((size_t)m << 11) + R] = sum2(acc[i][j]) + bih[R] + bhh[R];
            }
        }
    } else if (bid < 768) {
        int u = bid - 512;
        int dc = u & 1, b = (u >> 1) & 31, z = u >> 6;
        int d = dc * 256 + tid;
        float acc = 0.0f;
        int n0 = z * (NN / 4);
        for (int n = n0; n < n0 + NN / 4; n++) {
            if (getmask(pad, b * NN + n))
                acc += enc[((size_t)(b * NN + n)) * DD + d];
        }
        g_h0part[((z * BB) + b) * DD + d] = acc;
    } else if (bid < 800) {
        int b = bid - 768;
        int c1 = 0, c2 = 0;
        for (int n = tid; n < NN; n += 256) {
            c1 += getmask(pad, b * NN + n) ? 1 : 0;
            c2 += getmask(ptrm, b * NN + n) ? 1 : 0;
        }
        red1[tid] = c1; red2[tid] = c2; __syncthreads();
        for (int s = 128; s > 0; s >>= 1) {
            if (tid < s) { red1[tid] += red1[tid + s]; red2[tid] += red2[tid + s]; }
            __syncthreads();
        }
        if (tid == 0) { g_cntpad[b] = (float)red1[0]; g_cntptr[b] = (float)red2[0]; }
    } else {
        int zb = bid - 800;
        int idx = zb * 256 + tid;
        int stride = 512 * 256;
        float4 z4 = {0.f, 0.f, 0.f, 0.f};
        for (int i = idx; i < n4; i += stride) outz[i] = z4;
    }
}

// --------- hierarchical grid barrier: cluster.sync + 16-leader RMW counter ---
__device__ __forceinline__ void gbar(unsigned target16) {
    __threadfence();
    __syncthreads();
    asm volatile("barrier.cluster.arrive.aligned;" ::: "memory");
    asm volatile("barrier.cluster.wait.aligned;" ::: "memory");
    if (threadIdx.x == 0 && ctarank() == 0) {
        atomicAdd(&g_barcnt, 1u);
        while (atomicAdd(&g_barcnt, 0u) < target16) {}
        __threadfence();
    }
    asm volatile("barrier.cluster.arrive.aligned;" ::: "memory");
    asm volatile("barrier.cluster.wait.aligned;" ::: "memory");
    if (threadIdx.x == 0) __threadfence();   // CCTL.IVALL: flush this SM's L1
    __syncthreads();
}

// ---------------- persistent LSTM recurrence (R12 core, cluster barrier) -----
// 128 blocks x 256 threads, clusters of 8. block = (dt = bid>>3, s = bid&7).
__global__ void __launch_bounds__(256) __cluster_dims__(8, 1, 1)
lstm_persistent(const float* __restrict__ Whh) {
    __shared__ float Wsm[128][66];
    __shared__ float hs[32][66];
    int tid = threadIdx.x;
    int bid = blockIdx.x;
    int dt = bid >> 3, s = bid & 7;
    int k0 = s * 64;

    // W_hh slice into smem once
    for (int i = tid; i < 128 * 64; i += 256) {
        int lr = i >> 6, kk = i & 63;
        int R = ((lr >> 5) << 9) + (dt << 5) + (lr & 31);
        Wsm[lr][kk] = Whh[(size_t)R * 512 + k0 + kk];
    }

    // h0 finalize for owned (pb, pd)
    float creg = 0.f;
    int pd = 0, pb = 0;
    if (tid < 128) {
        int idx = bid * 128 + tid;
        pd = idx & 511; pb = idx >> 9;
        float ssum = 0.f;
        #pragma unroll
        for (int z = 0; z < 4; z++) ssum += g_h0part[(z * BB + pb) * DD + pd];
        float h0 = ssum / g_cntpad[pb];
        creg = h0;
        g_h[pb * DD + pd] = h0;
    }
    unsigned ep = 1;
    gbar(16 * ep);

    int tx = tid & 31;   // lr = tx + 32*j
    int ty = tid >> 5;   // b = ty*4 + i

    for (int t = 0; t < NSTEP; t++) {
        // stage h slice [32 b][64 k]
        for (int i = tid; i < 32 * 64; i += 256) {
            int b = i >> 6, kk = i & 63;
            hs[b][kk] = g_h[b * DD + k0 + kk];
        }
        __syncthreads();

        ull acc[4][4] = {};
        #pragma unroll 8
        for (int kp = 0; kp < 32; kp++) {
            ull hv[4], wv[4];
            #pragma unroll
            for (int i = 0; i < 4; i++) hv[i] = ld2(&hs[ty * 4 + i][kp * 2]);
            #pragma unroll
            for (int j = 0; j < 4; j++) wv[j] = ld2(&Wsm[tx + 32 * j][kp * 2]);
            #pragma unroll
            for (int i = 0; i < 4; i++)
                #pragma unroll
                for (int j = 0; j < 4; j++)
                    acc[i][j] = fma2(hv[i], wv[j], acc[i][j]);
        }
        #pragma unroll
        for (int i = 0; i < 4; i++) {
            int b = ty * 4 + i;
            #pragma unroll
            for (int j = 0; j < 4; j++)
                g_gp[((s * BB + b) << 11) + (j << 9) + (dt << 5) + tx] = sum2(acc[i][j]);
        }

        ep++; gbar(16 * ep);   // partials ready

        if (tid < 128) {
            const float* gx = g_gx + ((size_t)(t * BB + pb) << 11);
            float gi = gx[pd], gf = gx[512 + pd], gg = gx[1024 + pd], go = gx[1536 + pd];
            #pragma unroll
            for (int ss = 0; ss < 8; ss++) {
                const float* gp = g_gp + ((size_t)(ss * BB + pb) << 11);
                gi += gp[pd]; gf += gp[512 + pd]; gg += gp[1024 + pd]; go += gp[1536 + pd];
            }
            float cn = sigm(gf) * creg + sigm(gi) * tanhf(gg);
            float hn = sigm(go) * tanhf(cn);
            creg = cn;
            g_h[pb * DD + pd] = hn;
            g_Hall[((size_t)(t * BB + pb) << 9) + pd] = hn;
        }

        ep++; gbar(16 * ep);   // h ready
    }
}

// ---------------- hw: HW[m][n] = Hall[m]·W_att[n] ----------------------------
__global__ void __launch_bounds__(256) hw_kernel(const float* __restrict__ Watt) {
    __shared__ float As[64][66];
    __shared__ float Ws[64][66];
    int tid = threadIdx.x;
    int mbase = blockIdx.x * 64;
    int nbase = blockIdx.y * 64;
    int tx = tid & 15;
    int ty = tid >> 4;
    ull acc[4][4] = {};
    for (int k0 = 0; k0 < 512; k0 += 32) {
        __syncthreads();
        #pragma unroll
        for (int i = 0; i < 8; i++) {
            int lin = tid + 256 * i;
            int row = lin >> 5, c = lin & 31;
            int m = mbase + row;
            As[row][c] = (m < MM) ? g_Hall[((size_t)m << 9) + k0 + c] : 0.f;
            Ws[row][c] = Watt[(size_t)(nbase + row) * 512 + k0 + c];
        }
        __syncthreads();
        #pragma unroll
        for (int kp = 0; kp < 16; kp++) {
            ull av[4], wv[4];
            #pragma unroll
            for (int jj = 0; jj < 4; jj++) av[jj] = ld2(&As[ty * 4 + jj][kp * 2]);
            #pragma unroll
            for (int i = 0; i < 4; i++) wv[i] = ld2(&Ws[tx + 16 * i][kp * 2]);
            #pragma unroll
            for (int i = 0; i < 4; i++)
                #pragma unroll
                for (int jj = 0; jj < 4; jj++)
                    acc[i][jj] = fma2(av[jj], wv[i], acc[i][jj]);
        }
    }
    #pragma unroll
    for (int jj = 0; jj < 4; jj++) {
        int m = mbase + ty * 4 + jj;
        if (m >= MM) continue;
        #pragma unroll
        for (int i = 0; i < 4; i++)
            g_HW[((size_t)m << 9) + nbase + tx + 16 * i] = sum2(acc[i][jj]);
    }
}

// ---------------- scores[t][b][n] = enc[b][n]·HW[t*B+b] ----------------------
__global__ void __launch_bounds__(256) scores_kernel(const float* __restrict__ enc) {
    __shared__ float Es[256][34];
    __shared__ float Hs[32][34];
    int tid = threadIdx.x;
    int nbase = blockIdx.x << 8;
    int b = blockIdx.y;
    int nl = tid & 31;
    int tg = tid >> 5;
    ull acc[8][4] = {};
    for (int k0 = 0; k0 < 512; k0 += 32) {
        __syncthreads();
        #pragma unroll
        for (int i = 0; i < 16; i++) {
            int lin = tid + 256 * i;
            int row = lin >> 4, c2 = lin & 15;
            *(ull*)&Es[row][c2 * 2] =
                ld2(&enc[((size_t)(b * NN + nbase + row) << 9) + k0 + c2 * 2]);
        }
        #pragma unroll
        for (int i = 0; i < 2; i++) {
            int lin = tid + 256 * i;
            int row = lin >> 4, c2 = lin & 15;
            *(ull*)&Hs[row][c2 * 2] = (row < NSTEP)
                ? ld2(&g_HW[((size_t)(row * BB + b) << 9) + k0 + c2 * 2]) : 0ull;
        }
        __syncthreads();
        #pragma unroll
        for (int kp = 0; kp < 16; kp++) {
            ull ev[8], hv[4];
            #pragma unroll
            for (int i = 0; i < 8; i++) ev[i] = ld2(&Es[nl + 32 * i][kp * 2]);
            #pragma unroll
            for (int jj = 0; jj < 4; jj++) hv[jj] = ld2(&Hs[tg * 4 + jj][kp * 2]);
            #pragma unroll
            for (int i = 0; i < 8; i++)
                #pragma unroll
                for (int jj = 0; jj < 4; jj++)
                    acc[i][jj] = fma2(ev[i], hv[jj], acc[i][jj]);
        }
    }
    #pragma unroll
    for (int jj = 0; jj < 4; jj++) {
        int t = tg * 4 + jj;
        if (t >= NSTEP) continue;
        #pragma unroll
        for (int i = 0; i < 8; i++)
            g_scores[((size_t)(t * BB + b) << 11) + nbase + nl + 32 * i] = sum2(acc[i][jj]);
    }
}

// ---------------- softmax + threshold + scatter + eos ------------------------
__global__ void softmax_scatter_kernel(const void* ptrmask,
                                       const int* __restrict__ token_ids,
                                       const int* __restrict__ eosp,
                                       float* __restrict__ out) {
    int t = blockIdx.x, b = blockIdx.y, tid = threadIdx.x;
    __shared__ float sp[NN];
    __shared__ float red[256];
    const float* sc = g_scores + ((size_t)(t * BB) + b) * NN;

    float m = -1e30f;
    for (int n = tid; n < NN; n += 256) {
        bool pm = getmask(ptrmask, b * NN + n);
        float s = pm ? sc[n] : -1e30f;
        sp[n] = s;
        m = fmaxf(m, s);
    }
    red[tid] = m; __syncthreads();
    for (int s = 128; s > 0; s >>= 1) {
        if (tid < s) red[tid] = fmaxf(red[tid], red[tid + s]);
        __syncthreads();
    }
    m = red[0]; __syncthreads();

    float lsum = 0.f;
    for (int n = tid; n < NN; n += 256) {
        float s = sp[n];
        float e = (s > -1e29f) ? expf(s - m) : 0.f;
        sp[n] = e;
        lsum += e;
    }
    red[tid] = lsum; __syncthreads();
    for (int s = 128; s > 0; s >>= 1) {
        if (tid < s) red[tid] += red[tid + s];
        __syncthreads();
    }
    float sum = red[0];
    float thr = 1.0f / g_cntptr[b];
    float* orow = out + ((size_t)(t + 1)) * BB * VV + (size_t)b * VV;
    __syncthreads();

    float ks = 0.f;
    for (int n = tid; n < NN; n += 256) {
        float e = sp[n];
        if (e > 0.f) {
            float p = e / sum;
            if (p >= thr) {
                atomicAdd(&orow[token_ids[b * NN + n]], p);
                ks += p;
            }
        }
    }
    red[tid] = ks; __syncthreads();
    for (int s = 128; s > 0; s >>= 1) {
        if (tid < s) red[tid] += red[tid + s];
        __syncthreads();
    }
    if (tid == 0) {
        __threadfence();
        orow[eosp[0]] = 1.0f - red[0];
    }
}

// ---------------- host launcher ----------------------------------------------
extern "C" void kernel_launch(void* const* d_in, const int* in_sizes, int n_in,
                              void* d_out, int out_size) {
    const float* enc    = (const float*)d_in[0];
    const float* emb    = (const float*)d_in[1];
    const float* W_ih   = (const float*)d_in[2];
    const float* W_hh   = (const float*)d_in[3];
    const float* b_ih   = (const float*)d_in[4];
    const float* b_hh   = (const float*)d_in[5];
    const float* W_att  = (const float*)d_in[6];
    const void*  pad    = d_in[7];
    const void*  ptr    = d_in[8];
    const int*   tokid  = (const int*)d_in[9];
    const int*   target = (const int*)d_in[10];
    const int*   sosp   = (const int*)d_in[11];
    const int*   eosp   = (const int*)d_in[12];
    float* out = (float*)d_out;

    detect_kernel<<<1, 32>>>((const int*)pad);

    int n4 = (TT * BB * VV) / 4;
    mega_kernel<<<1312, 256>>>(emb, W_ih, b_ih, b_hh, target, sosp,
                               enc, pad, ptr, (float4*)out, n4);
    sos_kernel<<<1, 32>>>(out, sosp);

    lstm_persistent<<<128, 256>>>(W_hh);

    {
        dim3 g(16, 8);
        hw_kernel<<<g, 256>>>(W_att);
    }
    {
        dim3 g(8, BB);
        scores_kernel<<<g, 256>>>(enc);
    }
    {
        dim3 g(NSTEP, BB);
        softmax_scatter_kernel<<<g, 256>>>(ptr, tokid, eosp, out);
    }
}

// round 16
// speedup vs baseline: 1.2637x; 1.1502x over previous
#include <cuda_runtime.h>
#include <cuda_bf16.h>
#include <cstdint>

#define BB 32
#define NN 2048
#define DD 512
#define EE 512
#define VV 32000
#define TT 32
#define NSTEP 31
#define MM (NSTEP * BB)   // 992

typedef unsigned long long ull;

// ---------------- scratch ----------------------------------------------------
__device__ float g_h[BB * DD];
__device__ float g_Hall[MM * DD];
__device__ float g_HW[MM * DD];
__device__ float g_scores[MM * NN];         // 8.1 MB
__device__ float g_gx[MM * 4 * DD];         // 8.1 MB  (x-side gates + biases)
__device__ float g_gp[8 * BB * 4 * DD];     // 2 MB    (h-side partials)
__device__ float g_h0part[4 * BB * DD];
__device__ float g_cntpad[BB];
__device__ float g_cntptr[BB];
__device__ int   g_mask_mode;
__device__ unsigned g_barcnt;

// ---------------- helpers -----------------------------------------------------
__device__ __forceinline__ bool getmask(const void* p, int idx) {
    int m = g_mask_mode;
    if (m == 1) return ((const int*)p)[idx] != 0;
    if (m == 2) return ((const float*)p)[idx] != 0.0f;
    return ((const unsigned char*)p)[idx] != 0;
}
__device__ __forceinline__ float sigm(float x) { return 1.0f / (1.0f + expf(-x)); }

__device__ __forceinline__ ull ld2(const float* p) { return *(const ull*)p; }
__device__ __forceinline__ ull fma2(ull a, ull b, ull c) {
    ull d;
    asm("fma.rn.f32x2 %0, %1, %2, %3;" : "=l"(d) : "l"(a), "l"(b), "l"(c));
    return d;
}
__device__ __forceinline__ float sum2(ull v) {
    return __uint_as_float((unsigned)v) + __uint_as_float((unsigned)(v >> 32));
}

// ---------------- setup -------------------------------------------------------
__global__ void detect_kernel(const int* pad_as_int) {
    if (threadIdx.x == 0) {
        int v = pad_as_int[0];
        g_mask_mode = (v == 1) ? 1 : ((v == 0x3F800000) ? 2 : 0);
        g_barcnt = 0;
    }
}

__global__ void sos_kernel(float* out, const int* sosp) {
    int b = threadIdx.x;
    if (b < BB) out[(size_t)b * VV + sosp[0]] = 1.0f;
}

// ---------------- mega kernel: xgemm || h0part || counts || zero --------------
__global__ void __launch_bounds__(256) mega_kernel(
        const float* __restrict__ emb, const float* __restrict__ Wih,
        const float* __restrict__ bih, const float* __restrict__ bhh,
        const int* __restrict__ target, const int* __restrict__ sosp,
        const float* __restrict__ enc, const void* pad, const void* ptrm,
        float4* __restrict__ outz, int n4) {
    __shared__ float Ws[2][64][34];
    __shared__ float Xs[2][64][34];
    __shared__ int toks[64];
    __shared__ int red1[256], red2[256];
    int tid = threadIdx.x;
    int bid = blockIdx.x;

    if (bid < 512) {
        int Rbase = (bid & 31) * 64;
        int mbase = (bid >> 5) * 64;
        if (tid < 64) {
            int m = mbase + tid;
            int t = m >> 5, b = m & 31;
            int tok = sosp[0];
            if (m < MM && t > 0) tok = target[t * BB + b];
            toks[tid] = tok;
        }
        __syncthreads();
        #pragma unroll
        for (int q = 0; q < 2; q++) {
            int i = tid + 256 * q;
            int row = i >> 3, c4 = i & 7;
            float4 w = *(const float4*)&Wih[(size_t)(Rbase + row) * 512 + c4 * 4];
            float4 x = *(const float4*)&emb[(size_t)toks[row] * 512 + c4 * 4];
            *(float2*)&Ws[0][row][c4 * 4]     = make_float2(w.x, w.y);
            *(float2*)&Ws[0][row][c4 * 4 + 2] = make_float2(w.z, w.w);
            *(float2*)&Xs[0][row][c4 * 4]     = make_float2(x.x, x.y);
            *(float2*)&Xs[0][row][c4 * 4 + 2] = make_float2(x.z, x.w);
        }
        __syncthreads();
        int rl = tid & 15, mg = tid >> 4;
        ull acc[4][4] = {};
        float4 wst[2], xst[2];
        for (int kt = 0; kt < 16; kt++) {
            int cur = kt & 1;
            if (kt < 15) {
                int k0 = (kt + 1) * 32;
                #pragma unroll
                for (int q = 0; q < 2; q++) {
                    int i = tid + 256 * q;
                    int row = i >> 3, c4 = i & 7;
                    wst[q] = *(const float4*)&Wih[(size_t)(Rbase + row) * 512 + k0 + c4 * 4];
                    xst[q] = *(const float4*)&emb[(size_t)toks[row] * 512 + k0 + c4 * 4];
                }
            }
            #pragma unroll
            for (int kp = 0; kp < 16; kp++) {
                ull wv[4], xv[4];
                #pragma unroll
                for (int i = 0; i < 4; i++) wv[i] = ld2(&Ws[cur][rl + 16 * i][kp * 2]);
                #pragma unroll
                for (int j = 0; j < 4; j++) xv[j] = ld2(&Xs[cur][mg * 4 + j][kp * 2]);
                #pragma unroll
                for (int i = 0; i < 4; i++)
                    #pragma unroll
                    for (int j = 0; j < 4; j++)
                        acc[i][j] = fma2(wv[i], xv[j], acc[i][j]);
            }
            if (kt < 15) {
                __syncthreads();
                int nb = cur ^ 1;
                #pragma unroll
                for (int q = 0; q < 2; q++) {
                    int i = tid + 256 * q;
                    int row = i >> 3, c4 = i & 7;
                    *(float2*)&Ws[nb][row][c4 * 4]     = make_float2(wst[q].x, wst[q].y);
                    *(float2*)&Ws[nb][row][c4 * 4 + 2] = make_float2(wst[q].z, wst[q].w);
                    *(float2*)&Xs[nb][row][c4 * 4]     = make_float2(xst[q].x, xst[q].y);
                    *(float2*)&Xs[nb][row][c4 * 4 + 2] = make_float2(xst[q].z, xst[q].w);
                }
                __syncthreads();
            }
        }
        #pragma unroll
        for (int j = 0; j < 4; j++) {
            int m = mbase + mg * 4 + j;
            if (m >= MM) continue;
            #pragma unroll
            for (int i = 0; i < 4; i++) {
                int R = Rbase + rl + 16 * i;
                g_gx[((size_t)m << 11) + R] = sum2(acc[i][j]) + bih[R] + bhh[R];
            }
        }
    } else if (bid < 768) {
        int u = bid - 512;
        int dc = u & 1, b = (u >> 1) & 31, z = u >> 6;
        int d = dc * 256 + tid;
        float acc = 0.0f;
        int n0 = z * (NN / 4);
        for (int n = n0; n < n0 + NN / 4; n++) {
            if (getmask(pad, b * NN + n))
                acc += enc[((size_t)(b * NN + n)) * DD + d];
        }
        g_h0part[((z * BB) + b) * DD + d] = acc;
    } else if (bid < 800) {
        int b = bid - 768;
        int c1 = 0, c2 = 0;
        for (int n = tid; n < NN; n += 256) {
            c1 += getmask(pad, b * NN + n) ? 1 : 0;
            c2 += getmask(ptrm, b * NN + n) ? 1 : 0;
        }
        red1[tid] = c1; red2[tid] = c2; __syncthreads();
        for (int s = 128; s > 0; s >>= 1) {
            if (tid < s) { red1[tid] += red1[tid + s]; red2[tid] += red2[tid + s]; }
            __syncthreads();
        }
        if (tid == 0) { g_cntpad[b] = (float)red1[0]; g_cntptr[b] = (float)red2[0]; }
    } else {
        int zb = bid - 800;
        int idx = zb * 256 + tid;
        int stride = 512 * 256;
        float4 z4 = {0.f, 0.f, 0.f, 0.f};
        for (int i = idx; i < n4; i += stride) outz[i] = z4;
    }
}

// --------- grid barrier (R12-verbatim: single counter, RMW arrive + RMW poll) -
__device__ __forceinline__ void gbar(unsigned target) {
    __threadfence();
    __syncthreads();
    if (threadIdx.x == 0) {
        atomicAdd(&g_barcnt, 1u);
        while (atomicAdd(&g_barcnt, 0u) < target) {}
        __threadfence();
    }
    __syncthreads();
}

// ---------------- persistent LSTM recurrence + fused HW tail ------------------
// 128 blocks x 256 threads. block = (dt = bid>>3, s = bid&7).
// Tail: after final barrier, block bid computes HW tile (m=bid>>3, n=bid&7),
// aliasing the dead Wsm smem as As/Wh.
__global__ void __launch_bounds__(256) lstm_persistent(
        const float* __restrict__ Whh, const float* __restrict__ Watt) {
    __shared__ float Wsm[128][66];
    __shared__ float hs[32][66];
    int tid = threadIdx.x;
    int bid = blockIdx.x;
    int dt = bid >> 3, s = bid & 7;
    int k0 = s * 64;

    // W_hh slice into smem once
    for (int i = tid; i < 128 * 64; i += 256) {
        int lr = i >> 6, kk = i & 63;
        int R = ((lr >> 5) << 9) + (dt << 5) + (lr & 31);
        Wsm[lr][kk] = Whh[(size_t)R * 512 + k0 + kk];
    }

    // h0 finalize for owned (pb, pd)
    float creg = 0.f;
    int pd = 0, pb = 0;
    if (tid < 128) {
        int idx = bid * 128 + tid;
        pd = idx & 511; pb = idx >> 9;
        float ssum = 0.f;
        #pragma unroll
        for (int z = 0; z < 4; z++) ssum += g_h0part[(z * BB + pb) * DD + pd];
        float h0 = ssum / g_cntpad[pb];
        creg = h0;
        g_h[pb * DD + pd] = h0;
    }
    gbar(128);

    int tx = tid & 31;   // lr = tx + 32*j
    int ty = tid >> 5;   // b = ty*4 + i
    unsigned cnt = 128;

    for (int t = 0; t < NSTEP; t++) {
        // prefetch this step's gx gate values (independent of h / barriers)
        float pgi = 0.f, pgf = 0.f, pgg = 0.f, pgo = 0.f;
        if (tid < 128) {
            const float* gx = g_gx + ((size_t)(t * BB + pb) << 11);
            pgi = gx[pd]; pgf = gx[512 + pd]; pgg = gx[1024 + pd]; pgo = gx[1536 + pd];
        }

        // stage h slice [32 b][64 k]
        for (int i = tid; i < 32 * 64; i += 256) {
            int b = i >> 6, kk = i & 63;
            hs[b][kk] = g_h[b * DD + k0 + kk];
        }
        __syncthreads();

        ull acc[4][4] = {};
        #pragma unroll 8
        for (int kp = 0; kp < 32; kp++) {
            ull hv[4], wv[4];
            #pragma unroll
            for (int i = 0; i < 4; i++) hv[i] = ld2(&hs[ty * 4 + i][kp * 2]);
            #pragma unroll
            for (int j = 0; j < 4; j++) wv[j] = ld2(&Wsm[tx + 32 * j][kp * 2]);
            #pragma unroll
            for (int i = 0; i < 4; i++)
                #pragma unroll
                for (int j = 0; j < 4; j++)
                    acc[i][j] = fma2(hv[i], wv[j], acc[i][j]);
        }
        #pragma unroll
        for (int i = 0; i < 4; i++) {
            int b = ty * 4 + i;
            #pragma unroll
            for (int j = 0; j < 4; j++)
                g_gp[((s * BB + b) << 11) + (j << 9) + (dt << 5) + tx] = sum2(acc[i][j]);
        }

        cnt += 128; gbar(cnt);   // partials ready

        if (tid < 128) {
            float gi = pgi, gf = pgf, gg = pgg, go = pgo;
            #pragma unroll
            for (int ss = 0; ss < 8; ss++) {
                const float* gp = g_gp + ((size_t)(ss * BB + pb) << 11);
                gi += gp[pd]; gf += gp[512 + pd]; gg += gp[1024 + pd]; go += gp[1536 + pd];
            }
            float cn = sigm(gf) * creg + sigm(gi) * tanhf(gg);
            float hn = sigm(go) * tanhf(cn);
            creg = cn;
            g_h[pb * DD + pd] = hn;
            g_Hall[((size_t)(t * BB + pb) << 9) + pd] = hn;
        }

        cnt += 128; gbar(cnt);   // h ready
    }

    // ---------------- fused HW tail: HW[m][n] = Hall[m]·W_att[n] --------------
    // g_Hall fully visible after the final gbar. Alias dead Wsm as As / Wh.
    {
        float (*As)[66] = reinterpret_cast<float(*)[66]>(&Wsm[0]);
        float (*Wh)[66] = reinterpret_cast<float(*)[66]>(&Wsm[64]);
        int mbase = (bid >> 3) * 64;   // 16 m-tiles
        int nbase = (bid & 7) * 64;    // 8 n-tiles
        int hx = tid & 15;
        int hy = tid >> 4;
        ull acc[4][4] = {};
        for (int kk0 = 0; kk0 < 512; kk0 += 32) {
            __syncthreads();
            #pragma unroll
            for (int i = 0; i < 8; i++) {
                int lin = tid + 256 * i;
                int row = lin >> 5, c = lin & 31;
                int m = mbase + row;
                As[row][c] = (m < MM) ? g_Hall[((size_t)m << 9) + kk0 + c] : 0.f;
                Wh[row][c] = Watt[(size_t)(nbase + row) * 512 + kk0 + c];
            }
            __syncthreads();
            #pragma unroll
            for (int kp = 0; kp < 16; kp++) {
                ull av[4], wv[4];
                #pragma unroll
                for (int jj = 0; jj < 4; jj++) av[jj] = ld2(&As[hy * 4 + jj][kp * 2]);
                #pragma unroll
                for (int i = 0; i < 4; i++) wv[i] = ld2(&Wh[hx + 16 * i][kp * 2]);
                #pragma unroll
                for (int i = 0; i < 4; i++)
                    #pragma unroll
                    for (int jj = 0; jj < 4; jj++)
                        acc[i][jj] = fma2(av[jj], wv[i], acc[i][jj]);
            }
        }
        #pragma unroll
        for (int jj = 0; jj < 4; jj++) {
            int m = mbase + hy * 4 + jj;
            if (m >= MM) continue;
            #pragma unroll
            for (int i = 0; i < 4; i++)
                g_HW[((size_t)m << 9) + nbase + hx + 16 * i] = sum2(acc[i][jj]);
        }
    }
}

// ---------------- scores[t][b][n] = enc[b][n]·HW[t*B+b] ----------------------
__global__ void __launch_bounds__(256) scores_kernel(const float* __restrict__ enc) {
    __shared__ float Es[256][34];
    __shared__ float Hs[32][34];
    int tid = threadIdx.x;
    int nbase = blockIdx.x << 8;
    int b = blockIdx.y;
    int nl = tid & 31;
    int tg = tid >> 5;
    ull acc[8][4] = {};
    for (int k0 = 0; k0 < 512; k0 += 32) {
        __syncthreads();
        #pragma unroll
        for (int i = 0; i < 16; i++) {
            int lin = tid + 256 * i;
            int row = lin >> 4, c2 = lin & 15;
            *(ull*)&Es[row][c2 * 2] =
                ld2(&enc[((size_t)(b * NN + nbase + row) << 9) + k0 + c2 * 2]);
        }
        #pragma unroll
        for (int i = 0; i < 2; i++) {
            int lin = tid + 256 * i;
            int row = lin >> 4, c2 = lin & 15;
            *(ull*)&Hs[row][c2 * 2] = (row < NSTEP)
                ? ld2(&g_HW[((size_t)(row * BB + b) << 9) + k0 + c2 * 2]) : 0ull;
        }
        __syncthreads();
        #pragma unroll
        for (int kp = 0; kp < 16; kp++) {
            ull ev[8], hv[4];
            #pragma unroll
            for (int i = 0; i < 8; i++) ev[i] = ld2(&Es[nl + 32 * i][kp * 2]);
            #pragma unroll
            for (int jj = 0; jj < 4; jj++) hv[jj] = ld2(&Hs[tg * 4 + jj][kp * 2]);
            #pragma unroll
            for (int i = 0; i < 8; i++)
                #pragma unroll
                for (int jj = 0; jj < 4; jj++)
                    acc[i][jj] = fma2(ev[i], hv[jj], acc[i][jj]);
        }
    }
    #pragma unroll
    for (int jj = 0; jj < 4; jj++) {
        int t = tg * 4 + jj;
        if (t >= NSTEP) continue;
        #pragma unroll
        for (int i = 0; i < 8; i++)
            g_scores[((size_t)(t * BB + b) << 11) + nbase + nl + 32 * i] = sum2(acc[i][jj]);
    }
}

// ---------------- softmax + threshold + scatter + eos ------------------------
__global__ void softmax_scatter_kernel(const void* ptrmask,
                                       const int* __restrict__ token_ids,
                                       const int* __restrict__ eosp,
                                       float* __restrict__ out) {
    int t = blockIdx.x, b = blockIdx.y, tid = threadIdx.x;
    __shared__ float sp[NN];
    __shared__ float red[256];
    const float* sc = g_scores + ((size_t)(t * BB) + b) * NN;

    float m = -1e30f;
    for (int n = tid; n < NN; n += 256) {
        bool pm = getmask(ptrmask, b * NN + n);
        float s = pm ? sc[n] : -1e30f;
        sp[n] = s;
        m = fmaxf(m, s);
    }
    red[tid] = m; __syncthreads();
    for (int s = 128; s > 0; s >>= 1) {
        if (tid < s) red[tid] = fmaxf(red[tid], red[tid + s]);
        __syncthreads();
    }
    m = red[0]; __syncthreads();

    float lsum = 0.f;
    for (int n = tid; n < NN; n += 256) {
        float s = sp[n];
        float e = (s > -1e29f) ? expf(s - m) : 0.f;
        sp[n] = e;
        lsum += e;
    }
    red[tid] = lsum; __syncthreads();
    for (int s = 128; s > 0; s >>= 1) {
        if (tid < s) red[tid] += red[tid + s];
        __syncthreads();
    }
    float sum = red[0];
    float thr = 1.0f / g_cntptr[b];
    float* orow = out + ((size_t)(t + 1)) * BB * VV + (size_t)b * VV;
    __syncthreads();

    float ks = 0.f;
    for (int n = tid; n < NN; n += 256) {
        float e = sp[n];
        if (e > 0.f) {
            float p = e / sum;
            if (p >= thr) {
                atomicAdd(&orow[token_ids[b * NN + n]], p);
                ks += p;
            }
        }
    }
    red[tid] = ks; __syncthreads();
    for (int s = 128; s > 0; s >>= 1) {
        if (tid < s) red[tid] += red[tid + s];
        __syncthreads();
    }
    if (tid == 0) {
        __threadfence();
        orow[eosp[0]] = 1.0f - red[0];
    }
}

// ---------------- host launcher ----------------------------------------------
extern "C" void kernel_launch(void* const* d_in, const int* in_sizes, int n_in,
                              void* d_out, int out_size) {
    const float* enc    = (const float*)d_in[0];
    const float* emb    = (const float*)d_in[1];
    const float* W_ih   = (const float*)d_in[2];
    const float* W_hh   = (const float*)d_in[3];
    const float* b_ih   = (const float*)d_in[4];
    const float* b_hh   = (const float*)d_in[5];
    const float* W_att  = (const float*)d_in[6];
    const void*  pad    = d_in[7];
    const void*  ptr    = d_in[8];
    const int*   tokid  = (const int*)d_in[9];
    const int*   target = (const int*)d_in[10];
    const int*   sosp   = (const int*)d_in[11];
    const int*   eosp   = (const int*)d_in[12];
    float* out = (float*)d_out;

    detect_kernel<<<1, 32>>>((const int*)pad);

    int n4 = (TT * BB * VV) / 4;
    mega_kernel<<<1312, 256>>>(emb, W_ih, b_ih, b_hh, target, sosp,
                               enc, pad, ptr, (float4*)out, n4);
    sos_kernel<<<1, 32>>>(out, sosp);

    lstm_persistent<<<128, 256>>>(W_hh, W_att);

    {
        dim3 g(8, BB);
        scores_kernel<<<g, 256>>>(enc);
    }
    {
        dim3 g(NSTEP, BB);
        softmax_scatter_kernel<<<g, 256>>>(ptr, tokid, eosp, out);
    }
}

// round 17
// speedup vs baseline: 1.4223x; 1.1255x over previous
#include <cuda_runtime.h>
#include <cuda_bf16.h>
#include <cstdint>

#define BB 32
#define NN 2048
#define DD 512
#define EE 512
#define VV 32000
#define TT 32
#define NSTEP 31
#define MM (NSTEP * BB)   // 992

typedef unsigned long long ull;

// ---------------- scratch ----------------------------------------------------
__device__ ulonglong2 g_hq[2][128][32];     // h packed: [parity][d/4][b]
__device__ float g_Hall[MM * DD];
__device__ float g_HW[MM * DD];
__device__ float g_scores[MM * NN];         // 8.1 MB
__device__ float g_gx[MM * 4 * DD];         // 8.1 MB  (x-side gates + biases)
__device__ float g_h0part[4 * BB * DD];
__device__ float g_cntpad[BB];
__device__ float g_cntptr[BB];
__device__ int   g_mask_mode;
__device__ unsigned g_barcnt;

// ---------------- helpers -----------------------------------------------------
__device__ __forceinline__ bool getmask(const void* p, int idx) {
    int m = g_mask_mode;
    if (m == 1) return ((const int*)p)[idx] != 0;
    if (m == 2) return ((const float*)p)[idx] != 0.0f;
    return ((const unsigned char*)p)[idx] != 0;
}
__device__ __forceinline__ float sigm(float x) { return 1.0f / (1.0f + expf(-x)); }

__device__ __forceinline__ ull ld2(const float* p) { return *(const ull*)p; }
__device__ __forceinline__ ull fma2(ull a, ull b, ull c) {
    ull d;
    asm("fma.rn.f32x2 %0, %1, %2, %3;" : "=l"(d) : "l"(a), "l"(b), "l"(c));
    return d;
}
__device__ __forceinline__ float sum2(ull v) {
    return __uint_as_float((unsigned)v) + __uint_as_float((unsigned)(v >> 32));
}
__device__ __forceinline__ ull pack2(float lo, float hi) {
    return (ull)__float_as_uint(lo) | ((ull)__float_as_uint(hi) << 32);
}

// ---------------- setup -------------------------------------------------------
__global__ void detect_kernel(const int* pad_as_int) {
    if (threadIdx.x == 0) {
        int v = pad_as_int[0];
        g_mask_mode = (v == 1) ? 1 : ((v == 0x3F800000) ? 2 : 0);
        g_barcnt = 0;
    }
}

__global__ void sos_kernel(float* out, const int* sosp) {
    int b = threadIdx.x;
    if (b < BB) out[(size_t)b * VV + sosp[0]] = 1.0f;
}

// ---------------- mega kernel: xgemm || h0part || counts || zero --------------
__global__ void __launch_bounds__(256) mega_kernel(
        const float* __restrict__ emb, const float* __restrict__ Wih,
        const float* __restrict__ bih, const float* __restrict__ bhh,
        const int* __restrict__ target, const int* __restrict__ sosp,
        const float* __restrict__ enc, const void* pad, const void* ptrm,
        float4* __restrict__ outz, int n4) {
    __shared__ float Ws[2][64][34];
    __shared__ float Xs[2][64][34];
    __shared__ int toks[64];
    __shared__ int red1[256], red2[256];
    int tid = threadIdx.x;
    int bid = blockIdx.x;

    if (bid < 512) {
        int Rbase = (bid & 31) * 64;
        int mbase = (bid >> 5) * 64;
        if (tid < 64) {
            int m = mbase + tid;
            int t = m >> 5, b = m & 31;
            int tok = sosp[0];
            if (m < MM && t > 0) tok = target[t * BB + b];
            toks[tid] = tok;
        }
        __syncthreads();
        #pragma unroll
        for (int q = 0; q < 2; q++) {
            int i = tid + 256 * q;
            int row = i >> 3, c4 = i & 7;
            float4 w = *(const float4*)&Wih[(size_t)(Rbase + row) * 512 + c4 * 4];
            float4 x = *(const float4*)&emb[(size_t)toks[row] * 512 + c4 * 4];
            *(float2*)&Ws[0][row][c4 * 4]     = make_float2(w.x, w.y);
            *(float2*)&Ws[0][row][c4 * 4 + 2] = make_float2(w.z, w.w);
            *(float2*)&Xs[0][row][c4 * 4]     = make_float2(x.x, x.y);
            *(float2*)&Xs[0][row][c4 * 4 + 2] = make_float2(x.z, x.w);
        }
        __syncthreads();
        int rl = tid & 15, mg = tid >> 4;
        ull acc[4][4] = {};
        float4 wst[2], xst[2];
        for (int kt = 0; kt < 16; kt++) {
            int cur = kt & 1;
            if (kt < 15) {
                int k0 = (kt + 1) * 32;
                #pragma unroll
                for (int q = 0; q < 2; q++) {
                    int i = tid + 256 * q;
                    int row = i >> 3, c4 = i & 7;
                    wst[q] = *(const float4*)&Wih[(size_t)(Rbase + row) * 512 + k0 + c4 * 4];
                    xst[q] = *(const float4*)&emb[(size_t)toks[row] * 512 + k0 + c4 * 4];
                }
            }
            #pragma unroll
            for (int kp = 0; kp < 16; kp++) {
                ull wv[4], xv[4];
                #pragma unroll
                for (int i = 0; i < 4; i++) wv[i] = ld2(&Ws[cur][rl + 16 * i][kp * 2]);
                #pragma unroll
                for (int j = 0; j < 4; j++) xv[j] = ld2(&Xs[cur][mg * 4 + j][kp * 2]);
                #pragma unroll
                for (int i = 0; i < 4; i++)
                    #pragma unroll
                    for (int j = 0; j < 4; j++)
                        acc[i][j] = fma2(wv[i], xv[j], acc[i][j]);
            }
            if (kt < 15) {
                __syncthreads();
                int nb = cur ^ 1;
                #pragma unroll
                for (int q = 0; q < 2; q++) {
                    int i = tid + 256 * q;
                    int row = i >> 3, c4 = i & 7;
                    *(float2*)&Ws[nb][row][c4 * 4]     = make_float2(wst[q].x, wst[q].y);
                    *(float2*)&Ws[nb][row][c4 * 4 + 2] = make_float2(wst[q].z, wst[q].w);
                    *(float2*)&Xs[nb][row][c4 * 4]     = make_float2(xst[q].x, xst[q].y);
                    *(float2*)&Xs[nb][row][c4 * 4 + 2] = make_float2(xst[q].z, xst[q].w);
                }
                __syncthreads();
            }
        }
        #pragma unroll
        for (int j = 0; j < 4; j++) {
            int m = mbase + mg * 4 + j;
            if (m >= MM) continue;
            #pragma unroll
            for (int i = 0; i < 4; i++) {
                int R = Rbase + rl + 16 * i;
                g_gx[((size_t)m << 11) + R] = sum2(acc[i][j]) + bih[R] + bhh[R];
            }
        }
    } else if (bid < 768) {
        int u = bid - 512;
        int dc = u & 1, b = (u >> 1) & 31, z = u >> 6;
        int d = dc * 256 + tid;
        float acc = 0.0f;
        int n0 = z * (NN / 4);
        for (int n = n0; n < n0 + NN / 4; n++) {
            if (getmask(pad, b * NN + n))
                acc += enc[((size_t)(b * NN + n)) * DD + d];
        }
        g_h0part[((z * BB) + b) * DD + d] = acc;
    } else if (bid < 800) {
        int b = bid - 768;
        int c1 = 0, c2 = 0;
        for (int n = tid; n < NN; n += 256) {
            c1 += getmask(pad, b * NN + n) ? 1 : 0;
            c2 += getmask(ptrm, b * NN + n) ? 1 : 0;
        }
        red1[tid] = c1; red2[tid] = c2; __syncthreads();
        for (int s = 128; s > 0; s >>= 1) {
            if (tid < s) { red1[tid] += red1[tid + s]; red2[tid] += red2[tid + s]; }
            __syncthreads();
        }
        if (tid == 0) { g_cntpad[b] = (float)red1[0]; g_cntptr[b] = (float)red2[0]; }
    } else {
        int zb = bid - 800;
        int idx = zb * 256 + tid;
        int stride = 512 * 256;
        float4 z4 = {0.f, 0.f, 0.f, 0.f};
        for (int i = idx; i < n4; i += stride) outz[i] = z4;
    }
}

// ---------------- persistent LSTM: owner structure, ONE barrier/step ----------
// 128 blocks x 256 threads. Block j owns d-columns {4j..4j+3}; 16 gate rows
// R = g*512 + 4j + c over FULL k. Partials reduced block-locally (psum smem),
// pointwise local (gx prefetched), h exchanged via parity-buffered g_hq.
__global__ void __launch_bounds__(256) lstm_persistent(
        const float* __restrict__ Whh, const float* __restrict__ Watt) {
    __shared__ char arena[49664];
    ulonglong2 (*Wq)[128]  = (ulonglong2(*)[128])arena;          // [16][128] 32KB
    float (*psum)[16][32]  = (float(*)[16][32])(arena + 32768);  // [8][16][32] 16KB
    float (*hex)[32]       = (float(*)[32])(arena + 49152);      // [4][32] 512B
    int tid = threadIdx.x;
    int j = blockIdx.x;
    int lane = tid & 31, w = tid >> 5;

    // W rows once: r = g*4+c -> R = g*512 + 4j + c; Wq[r][q] = Whh[R][4q..4q+3]
    for (int i = tid; i < 16 * 128; i += 256) {
        int r = i >> 7, q = i & 127;
        int g = r >> 2, c = r & 3;
        int R = (g << 9) + 4 * j + c;
        Wq[r][q] = *(const ulonglong2*)&Whh[(size_t)R * 512 + 4 * q];
    }

    // h0 for owned columns
    float creg = 0.f;
    int pc = 0, pb = 0;
    if (tid < 128) {
        pc = tid >> 5; pb = tid & 31;
        int d = 4 * j + pc;
        float ssum = 0.f;
        #pragma unroll
        for (int z = 0; z < 4; z++) ssum += g_h0part[(z * BB + pb) * DD + d];
        float h0 = ssum / g_cntpad[pb];
        creg = h0;
        hex[pc][pb] = h0;
    }
    __syncthreads();
    if (tid < 32) {
        ulonglong2 u;
        u.x = pack2(hex[0][tid], hex[1][tid]);
        u.y = pack2(hex[2][tid], hex[3][tid]);
        g_hq[0][j][tid] = u;
    }
    // publish h0
    __threadfence(); __syncthreads();
    if (tid == 0) {
        atomicAdd(&g_barcnt, 1u);
        while (atomicAdd(&g_barcnt, 0u) < 128u) {}
        __threadfence();
    }
    __syncthreads();
    unsigned cnt = 128;

    for (int t = 0; t < NSTEP; t++) {
        // gx prefetch (independent of h)
        float pgi = 0.f, pgf = 0.f, pgg = 0.f, pgo = 0.f;
        if (tid < 128) {
            const float* gx = g_gx + ((size_t)(t * BB + pb) << 11) + 4 * j + pc;
            pgi = gx[0]; pgf = gx[512]; pgg = gx[1024]; pgo = gx[1536];
        }

        // GEMM: warp w covers q in [w*16, w*16+16); lane = b
        const longlong2* hq = (const longlong2*)&g_hq[t & 1][0][0];
        ull acc[16] = {};
        #pragma unroll
        for (int half = 0; half < 2; half++) {
            longlong2 hv[8];
            #pragma unroll
            for (int qq = 0; qq < 8; qq++)
                hv[qq] = __ldcg(&hq[(w * 16 + half * 8 + qq) * 32 + lane]);
            #pragma unroll
            for (int qq = 0; qq < 8; qq++) {
                int q = w * 16 + half * 8 + qq;
                ull hx = (ull)hv[qq].x, hy = (ull)hv[qq].y;
                #pragma unroll
                for (int r = 0; r < 16; r++) {
                    ulonglong2 wv = Wq[r][q];
                    acc[r] = fma2(hx, wv.x, acc[r]);
                    acc[r] = fma2(hy, wv.y, acc[r]);
                }
            }
        }
        #pragma unroll
        for (int r = 0; r < 16; r++) psum[w][r][lane] = sum2(acc[r]);
        __syncthreads();

        // pointwise (block-local): thread (pc, pb) -> d = 4j + pc
        float hn = 0.f;
        if (tid < 128) {
            float gi = pgi, gf = pgf, gg = pgg, go = pgo;
            #pragma unroll
            for (int w2 = 0; w2 < 8; w2++) {
                gi += psum[w2][pc][pb];
                gf += psum[w2][4 + pc][pb];
                gg += psum[w2][8 + pc][pb];
                go += psum[w2][12 + pc][pb];
            }
            float cn = sigm(gf) * creg + sigm(gi) * tanhf(gg);
            hn = sigm(go) * tanhf(cn);
            creg = cn;
            hex[pc][pb] = hn;
        }
        __syncthreads();
        if (tid < 32) {
            ulonglong2 u;
            u.x = pack2(hex[0][tid], hex[1][tid]);
            u.y = pack2(hex[2][tid], hex[3][tid]);
            g_hq[(t + 1) & 1][j][tid] = u;
        }

        // ONE barrier: arrive (publishes hq), overlap Hall store, poll
        __threadfence();
        __syncthreads();
        if (tid == 0) atomicAdd(&g_barcnt, 1u);
        if (tid < 128)
            g_Hall[((size_t)(t * BB + pb) << 9) + 4 * j + pc] = hn;
        if (tid == 0) {
            while (atomicAdd(&g_barcnt, 0u) < cnt + 128u) {}
            __threadfence();
        }
        __syncthreads();
        cnt += 128;
    }

    // extra barrier: publish final-step Hall stores
    __threadfence(); __syncthreads();
    if (tid == 0) {
        atomicAdd(&g_barcnt, 1u);
        while (atomicAdd(&g_barcnt, 0u) < cnt + 128u) {}
        __threadfence();
    }
    __syncthreads();

    // ---------------- fused HW tail: HW[m][n] = Hall[m]·W_att[n] --------------
    {
        float (*As)[66] = (float(*)[66])arena;
        float (*Wh)[66] = (float(*)[66])(arena + 64 * 66 * 4);
        int mbase = (j >> 3) * 64;   // 16 m-tiles
        int nbase = (j & 7) * 64;    // 8 n-tiles
        int hx = tid & 15;
        int hy = tid >> 4;
        ull acc[4][4] = {};
        for (int kk0 = 0; kk0 < 512; kk0 += 32) {
            __syncthreads();
            #pragma unroll
            for (int i = 0; i < 8; i++) {
                int lin = tid + 256 * i;
                int row = lin >> 5, c = lin & 31;
                int m = mbase + row;
                As[row][c] = (m < MM) ? g_Hall[((size_t)m << 9) + kk0 + c] : 0.f;
                Wh[row][c] = Watt[(size_t)(nbase + row) * 512 + kk0 + c];
            }
            __syncthreads();
            #pragma unroll
            for (int kp = 0; kp < 16; kp++) {
                ull av[4], wv[4];
                #pragma unroll
                for (int jj = 0; jj < 4; jj++) av[jj] = ld2(&As[hy * 4 + jj][kp * 2]);
                #pragma unroll
                for (int i = 0; i < 4; i++) wv[i] = ld2(&Wh[hx + 16 * i][kp * 2]);
                #pragma unroll
                for (int i = 0; i < 4; i++)
                    #pragma unroll
                    for (int jj = 0; jj < 4; jj++)
                        acc[i][jj] = fma2(av[jj], wv[i], acc[i][jj]);
            }
        }
        #pragma unroll
        for (int jj = 0; jj < 4; jj++) {
            int m = mbase + hy * 4 + jj;
            if (m >= MM) continue;
            #pragma unroll
            for (int i = 0; i < 4; i++)
                g_HW[((size_t)m << 9) + nbase + hx + 16 * i] = sum2(acc[i][jj]);
        }
    }
}

// ---------------- scores[t][b][n] = enc[b][n]·HW[t*B+b] ----------------------
__global__ void __launch_bounds__(256) scores_kernel(const float* __restrict__ enc) {
    __shared__ float Es[256][34];
    __shared__ float Hs[32][34];
    int tid = threadIdx.x;
    int nbase = blockIdx.x << 8;
    int b = blockIdx.y;
    int nl = tid & 31;
    int tg = tid >> 5;
    ull acc[8][4] = {};
    for (int k0 = 0; k0 < 512; k0 += 32) {
        __syncthreads();
        #pragma unroll
        for (int i = 0; i < 16; i++) {
            int lin = tid + 256 * i;
            int row = lin >> 4, c2 = lin & 15;
            *(ull*)&Es[row][c2 * 2] =
                ld2(&enc[((size_t)(b * NN + nbase + row) << 9) + k0 + c2 * 2]);
        }
        #pragma unroll
        for (int i = 0; i < 2; i++) {
            int lin = tid + 256 * i;
            int row = lin >> 4, c2 = lin & 15;
            *(ull*)&Hs[row][c2 * 2] = (row < NSTEP)
                ? ld2(&g_HW[((size_t)(row * BB + b) << 9) + k0 + c2 * 2]) : 0ull;
        }
        __syncthreads();
        #pragma unroll
        for (int kp = 0; kp < 16; kp++) {
            ull ev[8], hv[4];
            #pragma unroll
            for (int i = 0; i < 8; i++) ev[i] = ld2(&Es[nl + 32 * i][kp * 2]);
            #pragma unroll
            for (int jj = 0; jj < 4; jj++) hv[jj] = ld2(&Hs[tg * 4 + jj][kp * 2]);
            #pragma unroll
            for (int i = 0; i < 8; i++)
                #pragma unroll
                for (int jj = 0; jj < 4; jj++)
                    acc[i][jj] = fma2(ev[i], hv[jj], acc[i][jj]);
        }
    }
    #pragma unroll
    for (int jj = 0; jj < 4; jj++) {
        int t = tg * 4 + jj;
        if (t >= NSTEP) continue;
        #pragma unroll
        for (int i = 0; i < 8; i++)
            g_scores[((size_t)(t * BB + b) << 11) + nbase + nl + 32 * i] = sum2(acc[i][jj]);
    }
}

// ---------------- softmax + threshold + scatter + eos ------------------------
__global__ void softmax_scatter_kernel(const void* ptrmask,
                                       const int* __restrict__ token_ids,
                                       const int* __restrict__ eosp,
                                       float* __restrict__ out) {
    int t = blockIdx.x, b = blockIdx.y, tid = threadIdx.x;
    __shared__ float sp[NN];
    __shared__ float red[256];
    const float* sc = g_scores + ((size_t)(t * BB) + b) * NN;

    float m = -1e30f;
    for (int n = tid; n < NN; n += 256) {
        bool pm = getmask(ptrmask, b * NN + n);
        float s = pm ? sc[n] : -1e30f;
        sp[n] = s;
        m = fmaxf(m, s);
    }
    red[tid] = m; __syncthreads();
    for (int s = 128; s > 0; s >>= 1) {
        if (tid < s) red[tid] = fmaxf(red[tid], red[tid + s]);
        __syncthreads();
    }
    m = red[0]; __syncthreads();

    float lsum = 0.f;
    for (int n = tid; n < NN; n += 256) {
        float s = sp[n];
        float e = (s > -1e29f) ? expf(s - m) : 0.f;
        sp[n] = e;
        lsum += e;
    }
    red[tid] = lsum; __syncthreads();
    for (int s = 128; s > 0; s >>= 1) {
        if (tid < s) red[tid] += red[tid + s];
        __syncthreads();
    }
    float sum = red[0];
    float thr = 1.0f / g_cntptr[b];
    float* orow = out + ((size_t)(t + 1)) * BB * VV + (size_t)b * VV;
    __syncthreads();

    float ks = 0.f;
    for (int n = tid; n < NN; n += 256) {
        float e = sp[n];
        if (e > 0.f) {
            float p = e / sum;
            if (p >= thr) {
                atomicAdd(&orow[token_ids[b * NN + n]], p);
                ks += p;
            }
        }
    }
    red[tid] = ks; __syncthreads();
    for (int s = 128; s > 0; s >>= 1) {
        if (tid < s) red[tid] += red[tid + s];
        __syncthreads();
    }
    if (tid == 0) {
        __threadfence();
        orow[eosp[0]] = 1.0f - red[0];
    }
}

// ---------------- host launcher ----------------------------------------------
extern "C" void kernel_launch(void* const* d_in, const int* in_sizes, int n_in,
                              void* d_out, int out_size) {
    const float* enc    = (const float*)d_in[0];
    const float* emb    = (const float*)d_in[1];
    const float* W_ih   = (const float*)d_in[2];
    const float* W_hh   = (const float*)d_in[3];
    const float* b_ih   = (const float*)d_in[4];
    const float* b_hh   = (const float*)d_in[5];
    const float* W_att  = (const float*)d_in[6];
    const void*  pad    = d_in[7];
    const void*  ptr    = d_in[8];
    const int*   tokid  = (const int*)d_in[9];
    const int*   target = (const int*)d_in[10];
    const int*   sosp   = (const int*)d_in[11];
    const int*   eosp   = (const int*)d_in[12];
    float* out = (float*)d_out;

    detect_kernel<<<1, 32>>>((const int*)pad);

    int n4 = (TT * BB * VV) / 4;
    mega_kernel<<<1312, 256>>>(emb, W_ih, b_ih, b_hh, target, sosp,
                               enc, pad, ptr, (float4*)out, n4);
    sos_kernel<<<1, 32>>>(out, sosp);

    lstm_persistent<<<128, 256>>>(W_hh, W_att);

    {
        dim3 g(8, BB);
        scores_kernel<<<g, 256>>>(enc);
    }
    {
        dim3 g(NSTEP, BB);
        softmax_scatter_kernel<<<g, 256>>>(ptr, tokid, eosp, out);
    }
}